// round 1
// baseline (speedup 1.0000x reference)
#include <cuda_runtime.h>

#define BB 32
#define LL 8192
#define DD 256
#define MM (LL/2 + 1)   // 4097

// Scratch (no device allocation allowed)
__device__ float g_s[BB * LL];            // sigmoid scores, 1 MB
__device__ int   g_starts[BB * MM];       // compacted valley starts (sentinel = LL)

// ---------------------------------------------------------------------------
// Kernel 1: s[b,l] = sigmoid(dot(x[b,l,:], W) + bias). One warp per row.
// ---------------------------------------------------------------------------
__global__ void score_kernel(const float* __restrict__ x,
                             const float* __restrict__ W,
                             const float* __restrict__ bias) {
    __shared__ float sW[DD];
    int tid = threadIdx.x;
    for (int i = tid; i < DD; i += blockDim.x) sW[i] = W[i];
    __syncthreads();

    int warp = tid >> 5;
    int lane = tid & 31;
    long long row = (long long)blockIdx.x * 8 + warp;   // 8 warps per block
    if (row >= (long long)BB * LL) return;

    const float4* xr = (const float4*)(x + row * DD);
    const float4* wr = (const float4*)sW;
    float acc = 0.f;
#pragma unroll
    for (int c = 0; c < 2; c++) {
        float4 v = xr[lane * 2 + c];
        float4 w = wr[lane * 2 + c];
        acc += v.x * w.x + v.y * w.y + v.z * w.z + v.w * w.w;
    }
#pragma unroll
    for (int o = 16; o; o >>= 1) acc += __shfl_down_sync(0xffffffffu, acc, o);

    if (lane == 0) {
        float z = acc + bias[0];
        g_s[row] = 1.f / (1.f + expf(-z));
    }
}

// ---------------------------------------------------------------------------
// Kernel 2: per-batch strict-local-minima mask + stream compaction.
// One block (1024 threads) per batch. 8 positions per thread.
// Writes counts (as float) to the tail of the output buffer.
// ---------------------------------------------------------------------------
__global__ void compact_kernel(float* __restrict__ out_counts, int write_counts) {
    int b = blockIdx.x;
    const float* s = g_s + (long long)b * LL;
    int* starts = g_starts + (long long)b * MM;

    int tid  = threadIdx.x;           // 0..1023
    int lane = tid & 31;
    int wid  = tid >> 5;              // 0..31
    int base = tid * 8;

    bool mk[8];
    int cnt = 0;
#pragma unroll
    for (int i = 0; i < 8; i++) {
        int l = base + i;
        bool m;
        if (l == 0) {
            m = true;                                  // forced valley start
        } else if (l >= LL - 1) {
            m = false;                                 // s_after pad 0, s > 0
        } else {
            float c = s[l];
            m = (c < s[l - 1]) && (c < s[l + 1]);
        }
        mk[i] = m;
        cnt += m ? 1 : 0;
    }

    // warp inclusive scan of cnt
    int v = cnt;
#pragma unroll
    for (int o = 1; o < 32; o <<= 1) {
        int t = __shfl_up_sync(0xffffffffu, v, o);
        if (lane >= o) v += t;
    }
    __shared__ int warpsum[32];
    if (lane == 31) warpsum[wid] = v;
    __syncthreads();
    if (wid == 0) {
        int w = warpsum[lane];
#pragma unroll
        for (int o = 1; o < 32; o <<= 1) {
            int t = __shfl_up_sync(0xffffffffu, w, o);
            if (lane >= o) w += t;
        }
        warpsum[lane] = w;                              // inclusive over warps
    }
    __syncthreads();

    int offset = v - cnt + (wid ? warpsum[wid - 1] : 0);  // exclusive prefix
    int total  = warpsum[31];

#pragma unroll
    for (int i = 0; i < 8; i++) {
        if (mk[i]) starts[offset++] = base + i;
    }

    // sentinel-fill the tail
    for (int k = total + tid; k < MM; k += blockDim.x) starts[k] = LL;

    if (tid == 0 && write_counts) out_counts[b] = (float)total;
}

// ---------------------------------------------------------------------------
// Kernel 3: out[b,k,:] = (s[p]*x[p] + s[p+1]*x[p+1]) / max(s[p]+s[p+1], 1e-6)
// for p = starts[b,k]; zeros for sentinel rows. One float4 per thread.
// ---------------------------------------------------------------------------
__global__ void gather_kernel(const float* __restrict__ x,
                              float* __restrict__ out) {
    long long idx = (long long)blockIdx.x * blockDim.x + threadIdx.x; // vec4 idx
    const long long total4 = (long long)BB * MM * (DD / 4);
    if (idx >= total4) return;

    long long row = idx >> 6;      // (b*MM + k)
    int j = (int)(idx & 63);       // float4 column
    int b = (int)(row / MM);

    int p = g_starts[row];
    float4 o;
    if (p >= LL) {
        o.x = 0.f; o.y = 0.f; o.z = 0.f; o.w = 0.f;
    } else {
        long long xrow = (long long)b * LL + p;
        float s0 = g_s[xrow];
        bool h1 = (p + 1) < LL;
        float s1 = h1 ? g_s[xrow + 1] : 0.f;
        float den = fmaxf(s0 + s1, 1e-6f);

        const float4* x0 = (const float4*)(x + xrow * DD);
        float4 v0 = x0[j];
        float4 v1;
        if (h1) v1 = x0[(DD / 4) + j];
        else { v1.x = 0.f; v1.y = 0.f; v1.z = 0.f; v1.w = 0.f; }

        o.x = (s0 * v0.x + s1 * v1.x) / den;
        o.y = (s0 * v0.y + s1 * v1.y) / den;
        o.z = (s0 * v0.z + s1 * v1.z) / den;
        o.w = (s0 * v0.w + s1 * v1.w) / den;
    }
    ((float4*)out)[idx] = o;
}

// ---------------------------------------------------------------------------
extern "C" void kernel_launch(void* const* d_in, const int* in_sizes, int n_in,
                              void* d_out, int out_size) {
    const float* x    = (const float*)d_in[0];   // [B, L, D] f32
    // d_in[1]: olens (unused by the reference computation)
    const float* W    = (const float*)d_in[2];   // [D, 1] f32
    const float* bias = (const float*)d_in[3];   // [1] f32

    float* out = (float*)d_out;
    const long long out_elems = (long long)BB * MM * DD;   // 33,562,624
    int write_counts = (out_size >= (int)(out_elems + BB)) ? 1 : 0;

    // 1. scores: one warp per row, 8 rows per 256-thread block
    {
        int rows = BB * LL;
        int grid = (rows + 7) / 8;
        score_kernel<<<grid, 256>>>(x, W, bias);
    }
    // 2. mask + compaction + counts
    {
        compact_kernel<<<BB, 1024>>>(out + out_elems, write_counts);
    }
    // 3. gather + weighted average (+ zero-fill sentinel rows)
    {
        long long total4 = (long long)BB * MM * (DD / 4);
        int grid = (int)((total4 + 255) / 256);
        gather_kernel<<<grid, 256>>>(x, out);
    }
}